// round 5
// baseline (speedup 1.0000x reference)
#include <cuda_runtime.h>
#include <math.h>
#include <float.h>

#define BB 1024
#define LLN 50
#define EE 256
#define HH 256
#define KK2 512          // E + H
#define H4 1024
#define NEGV (-1e9f)
#define CEXPL 10.0f

typedef unsigned long long u64;

// ---------------- device scratch (no allocations allowed) ----------------
__device__ __align__(16) float g_e_gl[(size_t)LLN * BB * HH];  // 52.4 MB
__device__ __align__(16) float g_e_pt[(size_t)LLN * BB * HH];  // 52.4 MB
__device__ __align__(16) float g_xh0[BB * KK2];                // [x | h] ping
__device__ __align__(16) float g_xh1[BB * KK2];                // [x | h] pong
__device__ __align__(16) float g_c  [BB * HH];
__device__ __align__(16) float g_qgl[BB * HH];
__device__ __align__(16) float g_g  [BB * HH];                 // glimpse output (e-space)
__device__ __align__(16) float g_qpt[BB * HH];
__device__ __align__(16) float g_Wc [H4 * KK2];                // gate-interleaved [Wih|Whh]
__device__ __align__(16) float g_bc [H4];
__device__ unsigned char g_mask[BB * LLN];

// ---------------- packed fp32x2 FMA helpers (IEEE-exact) ------------------
__device__ __forceinline__ u64 pk2(float x, float y) {
    u64 r; asm("mov.b64 %0,{%1,%2};" : "=l"(r) : "f"(x), "f"(y)); return r;
}
__device__ __forceinline__ u64 pkdup(float x) {
    u64 r; asm("mov.b64 %0,{%1,%1};" : "=l"(r) : "f"(x)); return r;
}
__device__ __forceinline__ u64 ffma2(u64 a, u64 b, u64 c) {
    u64 d; asm("fma.rn.f32x2 %0,%1,%2,%3;" : "=l"(d) : "l"(a), "l"(b), "l"(c)); return d;
}
__device__ __forceinline__ float2 upk(u64 a) {
    float2 f; asm("mov.b64 {%0,%1},%2;" : "=f"(f.x), "=f"(f.y) : "l"(a)); return f;
}

// ---------------- fast transcendental (err ~1e-7; budget is 1e-3) ---------
__device__ __forceinline__ float fast_tanh(float x) {
    float ax = fabsf(x);
    float e  = __expf(ax + ax);                 // inf for big ax -> r = 1
    float r  = 1.f - __fdividef(2.f, e + 1.f);  // rcp.approx
    return copysignf(r, x);
}
__device__ __forceinline__ float sigm(float x) {
    return __fdividef(1.f, 1.f + __expf(-x));
}

// ---------------- init ---------------------------------------------------
__global__ void k_init(const float* __restrict__ dec, const float* __restrict__ h0,
                       const float* __restrict__ c0) {
    int i = blockIdx.x * blockDim.x + threadIdx.x;
    if (i < BB * KK2) {
        int b = i >> 9, k = i & 511;
        g_xh0[i] = (k < EE) ? dec[b * EE + k] : h0[b * HH + (k - EE)];
    }
    if (i < BB * HH)  g_c[i] = c0[i];
    if (i < BB * LLN) g_mask[i] = 0;
}

// ---------------- weight prep (one-time) ----------------------------------
__global__ void k_prep_lstm(const float* __restrict__ Wih, const float* __restrict__ Whh,
                            const float* __restrict__ bih, const float* __restrict__ bhh) {
    int r = blockIdx.x;
    int j = r >> 2, g = r & 3;
    int src = g * HH + j;
    for (int k = threadIdx.x; k < EE; k += blockDim.x)
        g_Wc[(size_t)r * KK2 + k] = Wih[(size_t)src * EE + k];
    for (int k = threadIdx.x; k < HH; k += blockDim.x)
        g_Wc[(size_t)r * KK2 + EE + k] = Whh[(size_t)src * HH + k];
    if (threadIdx.x == 0) g_bc[r] = bih[src] + bhh[src];
}

// ---------------- generic NT GEMM with G->reg prefetch --------------------
struct GA { const float* A; int lda; const float* W; const float* bias; float* C; };

template <int BM, int BN, int BK, int TM, int TN>
__global__ void gemm_multi(GA a0, GA a1, int N, int K) {
    constexpr int THREADS = (BM / TM) * (BN / TN);
    constexpr int A_LDS = BM * BK / THREADS / 4;
    constexpr int W_LDS = BN * BK / THREADS / 4;

    GA g = (blockIdx.z == 0) ? a0 : a1;

    __shared__ __align__(16) float As[BK][BM];
    __shared__ __align__(16) float Ws[BK][BN];

    const int tid = threadIdx.x;
    const int tx  = tid % (BN / TN);
    const int ty  = tid / (BN / TN);
    const int m0  = blockIdx.y * BM;
    const int n0  = blockIdx.x * BN;

    u64 acc[TM][TN / 2];
#pragma unroll
    for (int i = 0; i < TM; i++)
#pragma unroll
        for (int j = 0; j < TN / 2; j++) acc[i][j] = pk2(0.f, 0.f);

    float4 pa[A_LDS], pw[W_LDS];
    // prefetch first tile
#pragma unroll
    for (int i = 0; i < A_LDS; i++) {
        int li = tid + i * THREADS;
        pa[i] = *(const float4*)(g.A + (size_t)(m0 + li / (BK / 4)) * g.lda + (li % (BK / 4)) * 4);
    }
#pragma unroll
    for (int i = 0; i < W_LDS; i++) {
        int li = tid + i * THREADS;
        pw[i] = *(const float4*)(g.W + (size_t)(n0 + li / (BK / 4)) * K + (li % (BK / 4)) * 4);
    }

    for (int k0 = 0; k0 < K; k0 += BK) {
#pragma unroll
        for (int i = 0; i < A_LDS; i++) {
            int li = tid + i * THREADS;
            int r = li / (BK / 4), c4 = li % (BK / 4);
            As[c4 * 4 + 0][r] = pa[i].x; As[c4 * 4 + 1][r] = pa[i].y;
            As[c4 * 4 + 2][r] = pa[i].z; As[c4 * 4 + 3][r] = pa[i].w;
        }
#pragma unroll
        for (int i = 0; i < W_LDS; i++) {
            int li = tid + i * THREADS;
            int r = li / (BK / 4), c4 = li % (BK / 4);
            Ws[c4 * 4 + 0][r] = pw[i].x; Ws[c4 * 4 + 1][r] = pw[i].y;
            Ws[c4 * 4 + 2][r] = pw[i].z; Ws[c4 * 4 + 3][r] = pw[i].w;
        }
        __syncthreads();

        if (k0 + BK < K) {
#pragma unroll
            for (int i = 0; i < A_LDS; i++) {
                int li = tid + i * THREADS;
                pa[i] = *(const float4*)(g.A + (size_t)(m0 + li / (BK / 4)) * g.lda
                                         + k0 + BK + (li % (BK / 4)) * 4);
            }
#pragma unroll
            for (int i = 0; i < W_LDS; i++) {
                int li = tid + i * THREADS;
                pw[i] = *(const float4*)(g.W + (size_t)(n0 + li / (BK / 4)) * K
                                         + k0 + BK + (li % (BK / 4)) * 4);
            }
        }

#pragma unroll
        for (int kk = 0; kk < BK; kk++) {
            u64 bp[TN / 2];
#pragma unroll
            for (int j = 0; j < TN / 4; j++) {
                float4 wv = *(const float4*)&Ws[kk][tx * TN + j * 4];
                bp[2 * j]     = pk2(wv.x, wv.y);
                bp[2 * j + 1] = pk2(wv.z, wv.w);
            }
#pragma unroll
            for (int i = 0; i < TM; i += 4) {
                float4 av = *(const float4*)&As[kk][ty * TM + i];
                u64 q0 = pkdup(av.x), q1 = pkdup(av.y), q2 = pkdup(av.z), q3 = pkdup(av.w);
#pragma unroll
                for (int j = 0; j < TN / 2; j++) {
                    acc[i + 0][j] = ffma2(q0, bp[j], acc[i + 0][j]);
                    acc[i + 1][j] = ffma2(q1, bp[j], acc[i + 1][j]);
                    acc[i + 2][j] = ffma2(q2, bp[j], acc[i + 2][j]);
                    acc[i + 3][j] = ffma2(q3, bp[j], acc[i + 3][j]);
                }
            }
        }
        __syncthreads();
    }

    const int n = n0 + tx * TN;
    float bb[TN];
#pragma unroll
    for (int j = 0; j < TN; j++) bb[j] = g.bias[n + j];
#pragma unroll
    for (int i = 0; i < TM; i++) {
        int m = m0 + ty * TM + i;
#pragma unroll
        for (int j = 0; j < TN / 4; j++) {
            float2 u0 = upk(acc[i][2 * j]);
            float2 u1 = upk(acc[i][2 * j + 1]);
            float4 r;
            r.x = u0.x + bb[4 * j];     r.y = u0.y + bb[4 * j + 1];
            r.z = u1.x + bb[4 * j + 2]; r.w = u1.y + bb[4 * j + 3];
            *(float4*)(g.C + (size_t)m * N + n + 4 * j) = r;
        }
    }
}

// ---------------- LSTM: gates GEMM + cell fused ----------------------------
// BM=64, BN=32, BK=16, TM=4, TN=4, 128 threads -> grid 32x16 = 512 CTAs.
__global__ void k_lstm(const float* __restrict__ A, float* __restrict__ xh_next) {
    constexpr int BM = 64, BN = 32, BK = 16, TM = 4;
    constexpr int THREADS = 128;

    __shared__ __align__(16) float As[BK][BM];
    __shared__ __align__(16) float Ws[BK][BN];

    const int tid = threadIdx.x;
    const int tx  = tid % 8;            // BN/TN = 8
    const int ty  = tid / 8;            // 0..15
    const int m0  = blockIdx.y * BM;
    const int n0  = blockIdx.x * BN;

    u64 acc[TM][2];
#pragma unroll
    for (int i = 0; i < TM; i++) { acc[i][0] = pk2(0.f, 0.f); acc[i][1] = pk2(0.f, 0.f); }

    float4 pa[2], pw;
    // A_LDS = 64*16/128/4 = 2 ; W_LDS = 32*16/128/4 = 1
#pragma unroll
    for (int i = 0; i < 2; i++) {
        int li = tid + i * THREADS;
        pa[i] = *(const float4*)(A + (size_t)(m0 + li / 4) * KK2 + (li % 4) * 4);
    }
    pw = *(const float4*)(g_Wc + (size_t)(n0 + tid / 4) * KK2 + (tid % 4) * 4);

    for (int k0 = 0; k0 < KK2; k0 += BK) {
#pragma unroll
        for (int i = 0; i < 2; i++) {
            int li = tid + i * THREADS;
            int r = li / 4, c4 = li % 4;
            As[c4 * 4 + 0][r] = pa[i].x; As[c4 * 4 + 1][r] = pa[i].y;
            As[c4 * 4 + 2][r] = pa[i].z; As[c4 * 4 + 3][r] = pa[i].w;
        }
        {
            int r = tid / 4, c4 = tid % 4;
            Ws[c4 * 4 + 0][r] = pw.x; Ws[c4 * 4 + 1][r] = pw.y;
            Ws[c4 * 4 + 2][r] = pw.z; Ws[c4 * 4 + 3][r] = pw.w;
        }
        __syncthreads();

        if (k0 + BK < KK2) {
#pragma unroll
            for (int i = 0; i < 2; i++) {
                int li = tid + i * THREADS;
                pa[i] = *(const float4*)(A + (size_t)(m0 + li / 4) * KK2
                                         + k0 + BK + (li % 4) * 4);
            }
            pw = *(const float4*)(g_Wc + (size_t)(n0 + tid / 4) * KK2
                                  + k0 + BK + (tid % 4) * 4);
        }

#pragma unroll
        for (int kk = 0; kk < BK; kk++) {
            float4 bv = *(const float4*)&Ws[kk][tx * 4];
            u64 bp0 = pk2(bv.x, bv.y);
            u64 bp1 = pk2(bv.z, bv.w);
            float4 av = *(const float4*)&As[kk][ty * TM];
            u64 q0 = pkdup(av.x), q1 = pkdup(av.y), q2 = pkdup(av.z), q3 = pkdup(av.w);
            acc[0][0] = ffma2(q0, bp0, acc[0][0]);
            acc[0][1] = ffma2(q0, bp1, acc[0][1]);
            acc[1][0] = ffma2(q1, bp0, acc[1][0]);
            acc[1][1] = ffma2(q1, bp1, acc[1][1]);
            acc[2][0] = ffma2(q2, bp0, acc[2][0]);
            acc[2][1] = ffma2(q2, bp1, acc[2][1]);
            acc[3][0] = ffma2(q3, bp0, acc[3][0]);
            acc[3][1] = ffma2(q3, bp1, acc[3][1]);
        }
        __syncthreads();
    }

    const int n = n0 + tx * 4;
    const int j = n >> 2;               // hidden unit index
    float bi = g_bc[n], bf = g_bc[n + 1], bg = g_bc[n + 2], bo = g_bc[n + 3];
#pragma unroll
    for (int i = 0; i < TM; i++) {
        int m = m0 + ty * TM + i;
        float2 u0 = upk(acc[i][0]);
        float2 u1 = upk(acc[i][1]);
        float gi = u0.x + bi, gf = u0.y + bf, gg = u1.x + bg, go = u1.y + bo;
        float c  = g_c[(size_t)m * HH + j];
        float c2 = sigm(gf) * c + sigm(gi) * fast_tanh(gg);
        g_c[(size_t)m * HH + j] = c2;
        xh_next[(size_t)m * KK2 + EE + j] = sigm(go) * fast_tanh(c2);
    }
}

// ------ glimpse attention: u, masked softmax, combine IN e-SPACE -> g ------
__global__ void k_attn_gl(const float* __restrict__ v) {
    int b = blockIdx.x, tid = threadIdx.x, lane = tid & 31, w = tid >> 5;
    __shared__ __align__(16) float qs[HH], vs[HH];
    __shared__ float sp[LLN];
    __shared__ float s_inv;
    qs[tid] = g_qgl[(size_t)b * HH + tid];
    vs[tid] = v[tid];
    __syncthreads();

    const float* eb = g_e_gl + (size_t)b * HH;
    const float4* q4 = (const float4*)qs;
    const float4* v4 = (const float4*)vs;
    for (int l = w; l < LLN; l += 8) {
        const float4* er = (const float4*)(eb + (size_t)l * BB * HH);
        float4 e0 = er[lane * 2], e1 = er[lane * 2 + 1];
        float4 q0 = q4[lane * 2], q1 = q4[lane * 2 + 1];
        float4 vv0 = v4[lane * 2], vv1 = v4[lane * 2 + 1];
        float s = fast_tanh(q0.x + e0.x) * vv0.x + fast_tanh(q0.y + e0.y) * vv0.y
                + fast_tanh(q0.z + e0.z) * vv0.z + fast_tanh(q0.w + e0.w) * vv0.w
                + fast_tanh(q1.x + e1.x) * vv1.x + fast_tanh(q1.y + e1.y) * vv1.y
                + fast_tanh(q1.z + e1.z) * vv1.z + fast_tanh(q1.w + e1.w) * vv1.w;
#pragma unroll
        for (int o = 16; o; o >>= 1) s += __shfl_xor_sync(0xffffffffu, s, o);
        if (lane == 0) sp[l] = g_mask[b * LLN + l] ? NEGV : s;
    }
    __syncthreads();
    if (w == 0) {
        float a  = (lane < LLN) ? sp[lane] : -FLT_MAX;
        float bb = (lane + 32 < LLN) ? sp[lane + 32] : -FLT_MAX;
        float m = fmaxf(a, bb);
#pragma unroll
        for (int o = 16; o; o >>= 1) m = fmaxf(m, __shfl_xor_sync(0xffffffffu, m, o));
        float ea  = (lane < LLN) ? __expf(a - m) : 0.f;
        float eb2 = (lane + 32 < LLN) ? __expf(bb - m) : 0.f;
        if (lane < LLN) sp[lane] = ea;
        if (lane + 32 < LLN) sp[lane + 32] = eb2;
        float s = ea + eb2;
#pragma unroll
        for (int o = 16; o; o >>= 1) s += __shfl_xor_sync(0xffffffffu, s, o);
        if (lane == 0) s_inv = __fdividef(1.f, s);
    }
    __syncthreads();
    float inv = s_inv;
    const float* ec = eb + tid;
    float a0 = 0.f, a1 = 0.f;
#pragma unroll
    for (int l = 0; l < LLN; l += 2) {
        a0 = fmaf(sp[l],     ec[(size_t) l      * BB * HH], a0);
        a1 = fmaf(sp[l + 1], ec[(size_t)(l + 1) * BB * HH], a1);
    }
    g_g[(size_t)b * HH + tid] = (a0 + a1) * inv;
}

// ---- pointer attention: log_softmax (-> out), argmax, gather, mask --------
__global__ void k_attn_pt(const float* __restrict__ v, const float* __restrict__ emb,
                          float* __restrict__ out, float* __restrict__ sel_out,
                          int t, int wsel, float* __restrict__ xh_next) {
    int b = blockIdx.x, tid = threadIdx.x, lane = tid & 31, w = tid >> 5;
    __shared__ __align__(16) float qs[HH], vs[HH];
    __shared__ float sp[LLN];
    __shared__ float s_lse;
    __shared__ int s_idx;
    qs[tid] = g_qpt[(size_t)b * HH + tid];
    vs[tid] = v[tid];
    __syncthreads();

    const float* eb = g_e_pt + (size_t)b * HH;
    const float4* q4 = (const float4*)qs;
    const float4* v4 = (const float4*)vs;
    for (int l = w; l < LLN; l += 8) {
        const float4* er = (const float4*)(eb + (size_t)l * BB * HH);
        float4 e0 = er[lane * 2], e1 = er[lane * 2 + 1];
        float4 q0 = q4[lane * 2], q1 = q4[lane * 2 + 1];
        float4 vv0 = v4[lane * 2], vv1 = v4[lane * 2 + 1];
        float s = fast_tanh(q0.x + e0.x) * vv0.x + fast_tanh(q0.y + e0.y) * vv0.y
                + fast_tanh(q0.z + e0.z) * vv0.z + fast_tanh(q0.w + e0.w) * vv0.w
                + fast_tanh(q1.x + e1.x) * vv1.x + fast_tanh(q1.y + e1.y) * vv1.y
                + fast_tanh(q1.z + e1.z) * vv1.z + fast_tanh(q1.w + e1.w) * vv1.w;
#pragma unroll
        for (int o = 16; o; o >>= 1) s += __shfl_xor_sync(0xffffffffu, s, o);
        if (lane == 0) sp[l] = g_mask[b * LLN + l] ? NEGV : (CEXPL * fast_tanh(s));
    }
    __syncthreads();
    if (w == 0) {
        float a  = (lane < LLN) ? sp[lane] : -FLT_MAX;           int ia = lane;
        float bb = (lane + 32 < LLN) ? sp[lane + 32] : -FLT_MAX; int ib = lane + 32;
        float m; int mi;
        if (bb > a) { m = bb; mi = ib; } else { m = a; mi = ia; }
#pragma unroll
        for (int o = 16; o; o >>= 1) {
            float om = __shfl_xor_sync(0xffffffffu, m, o);
            int   oi = __shfl_xor_sync(0xffffffffu, mi, o);
            if (om > m || (om == m && oi < mi)) { m = om; mi = oi; }
        }
        float s = ((lane < LLN) ? __expf(a - m) : 0.f)
                + ((lane + 32 < LLN) ? __expf(bb - m) : 0.f);
#pragma unroll
        for (int o = 16; o; o >>= 1) s += __shfl_xor_sync(0xffffffffu, s, o);
        if (lane == 0) { s_lse = m + __logf(s); s_idx = mi; }
    }
    __syncthreads();
    int idx = s_idx; float lse = s_lse;
    if (tid < LLN)
        out[((size_t)b * LLN + t) * LLN + tid] = sp[tid] - lse;
    xh_next[(size_t)b * KK2 + tid] = emb[((size_t)idx * BB + b) * EE + tid];
    if (tid == 0) {
        g_mask[b * LLN + idx] = 1;       // mask for NEXT step
        int cnt = 0;
#pragma unroll
        for (int l = 0; l < LLN; l++) cnt += g_mask[b * LLN + l];
        if (cnt == LLN) g_mask[b * LLN + LLN - 1] = 0;   // ref's all-true reset
        if (wsel) sel_out[b * LLN + t] = (float)idx;
    }
}

// -------------------------------- launch ----------------------------------
extern "C" void kernel_launch(void* const* d_in, const int* in_sizes, int n_in,
                              void* d_out, int out_size) {
    (void)in_sizes; (void)n_in;
    const float* dec  = (const float*)d_in[0];
    const float* emb  = (const float*)d_in[1];
    const float* h0   = (const float*)d_in[2];
    const float* c0   = (const float*)d_in[3];
    const float* ctx  = (const float*)d_in[4];
    const float* Wih  = (const float*)d_in[6];
    const float* Whh  = (const float*)d_in[7];
    const float* bih  = (const float*)d_in[8];
    const float* bhh  = (const float*)d_in[9];
    const float* glWq = (const float*)d_in[10];
    const float* glbq = (const float*)d_in[11];
    const float* glWr = (const float*)d_in[12];
    const float* glbr = (const float*)d_in[13];
    const float* glv  = (const float*)d_in[14];
    const float* ptWq = (const float*)d_in[15];
    const float* ptbq = (const float*)d_in[16];
    const float* ptWr = (const float*)d_in[17];
    const float* ptbr = (const float*)d_in[18];
    const float* ptv  = (const float*)d_in[19];
    float* out = (float*)d_out;

    float *pe_gl, *pe_pt, *pxh0, *pxh1, *pqgl, *pqpt, *pg;
    cudaGetSymbolAddress((void**)&pe_gl, g_e_gl);
    cudaGetSymbolAddress((void**)&pe_pt, g_e_pt);
    cudaGetSymbolAddress((void**)&pxh0,  g_xh0);
    cudaGetSymbolAddress((void**)&pxh1,  g_xh1);
    cudaGetSymbolAddress((void**)&pqgl,  g_qgl);
    cudaGetSymbolAddress((void**)&pqpt,  g_qpt);
    cudaGetSymbolAddress((void**)&pg,    g_g);

    k_init<<<2048, 256>>>(dec, h0, c0);
    k_prep_lstm<<<H4, 256>>>(Wih, Whh, bih, bhh);

    // Time-invariant projections (z=2): e_gl = ctx@glWr^T+glbr ; e_pt = ctx@ptWr^T+ptbr
    {
        GA a0{ctx, HH, glWr, glbr, pe_gl};
        GA a1{ctx, HH, ptWr, ptbr, pe_pt};
        dim3 g(HH / 128, (LLN * BB) / 128, 2);
        gemm_multi<128, 128, 16, 8, 8><<<g, 256>>>(a0, a1, HH, HH);
    }

    const size_t BLLL = (size_t)BB * LLN * LLN;
    const int wsel = (out_size >= (int)(BLLL + (size_t)BB * LLN)) ? 1 : 0;

    float* xh[2] = {pxh0, pxh1};
    for (int t = 0; t < LLN; t++) {
        float* cur = xh[t & 1];
        float* nxt = xh[(t + 1) & 1];
        // LSTM gates GEMM + fused cell: 512 CTAs (2048 warps) + prefetch
        k_lstm<<<dim3(H4 / 32, BB / 64), 128>>>(cur, nxt);
        // q_gl = h_t @ glWq^T + glbq  (256 CTAs of 64 thr)
        {
            GA a{nxt + EE, KK2, glWq, glbq, pqgl};
            gemm_multi<32, 32, 16, 4, 4><<<dim3(HH / 32, BB / 32, 1), 64>>>(a, a, HH, HH);
        }
        // glimpse attention -> g (combine in e-space)
        k_attn_gl<<<BB, HH>>>(glv);
        // q_pt = g @ ptWq^T + ptbq
        {
            GA a{pg, HH, ptWq, ptbq, pqpt};
            gemm_multi<32, 32, 16, 4, 4><<<dim3(HH / 32, BB / 32, 1), 64>>>(a, a, HH, HH);
        }
        // pointer attention: log_p -> out, argmax, gather x_{t+1}, mask update
        k_attn_pt<<<BB, HH>>>(ptv, emb, out, out + BLLL, t, wsel, nxt);
    }
}

// round 6
// speedup vs baseline: 1.5172x; 1.5172x over previous
#include <cuda_runtime.h>
#include <math.h>
#include <float.h>

#define BB 1024
#define LLN 50
#define EE 256
#define HH 256
#define KK2 512          // E + H
#define H4 1024
#define NEGV (-1e9f)
#define CEXPL 10.0f

typedef unsigned long long u64;

// ---------------- device scratch (no allocations allowed) ----------------
__device__ __align__(16) float g_e_gl[(size_t)LLN * BB * HH];  // 52.4 MB
__device__ __align__(16) float g_e_pt[(size_t)LLN * BB * HH];  // 52.4 MB
__device__ __align__(16) float g_xh0[BB * KK2];                // [x | h] ping
__device__ __align__(16) float g_xh1[BB * KK2];                // [x | h] pong
__device__ __align__(16) float g_c  [BB * HH];
__device__ __align__(16) float g_qgl[BB * HH];
__device__ __align__(16) float g_g  [BB * HH];
__device__ __align__(16) float g_qpt[BB * HH];
__device__ __align__(16) float g_G1 [BB * H4];                 // split-K partial (x)
__device__ __align__(16) float g_G2 [BB * H4];                 // split-K partial (h)
__device__ __align__(16) float g_Wc [H4 * KK2];                // gate-interleaved [Wih|Whh]
__device__ __align__(16) float g_bc [H4];
__device__ __align__(16) float g_zero[H4];                     // zero bias (static init = 0)
__device__ unsigned char g_mask[BB * LLN];

// ---------------- packed fp32x2 FMA helpers (IEEE-exact) ------------------
__device__ __forceinline__ u64 pk2(float x, float y) {
    u64 r; asm("mov.b64 %0,{%1,%2};" : "=l"(r) : "f"(x), "f"(y)); return r;
}
__device__ __forceinline__ u64 pkdup(float x) {
    u64 r; asm("mov.b64 %0,{%1,%1};" : "=l"(r) : "f"(x)); return r;
}
__device__ __forceinline__ u64 ffma2(u64 a, u64 b, u64 c) {
    u64 d; asm("fma.rn.f32x2 %0,%1,%2,%3;" : "=l"(d) : "l"(a), "l"(b), "l"(c)); return d;
}
__device__ __forceinline__ float2 upk(u64 a) {
    float2 f; asm("mov.b64 {%0,%1},%2;" : "=f"(f.x), "=f"(f.y) : "l"(a)); return f;
}

// ---------------- FMA-pipe exp2 (deg-7 Horner, rel err ~1e-8) -------------
// Input y must already be clamped to [-126, 126].
__device__ __forceinline__ float fexp2(float y) {
    float k = y + 12582912.0f;              // RN round-to-int via magic
    float f = y - (k - 12582912.0f);        // f in [-0.5, 0.5], exact
    float p =            1.5252734e-5f;
    p = fmaf(p, f, 1.5403530e-4f);
    p = fmaf(p, f, 1.3333558e-3f);
    p = fmaf(p, f, 9.6181291e-3f);
    p = fmaf(p, f, 5.5504109e-2f);
    p = fmaf(p, f, 2.4022651e-1f);
    p = fmaf(p, f, 6.9314718e-1f);
    p = fmaf(p, f, 1.0f);
    // exponent: bits(k) = 0x4B400000 + n  ->  (n + 127) << 23
    float sc = __int_as_float((__float_as_int(k) - 1262485377) << 23);
    return p * sc;
}

// tanh with 1 MUFU (rcp) instead of 2 (ex2 + rcp); rel err ~1e-7
__device__ __forceinline__ float fast_tanh(float x) {
    float ax = fabsf(x);
    float y  = fminf(ax * 2.8853901f, 126.0f);   // 2*log2(e)*ax
    float e2 = fexp2(y);
    float r  = 1.0f - __fdividef(2.0f, e2 + 1.0f);
    return copysignf(r, x);
}
__device__ __forceinline__ float sigm(float x) {
    float y = fminf(fmaxf(-x * 1.4426950f, -126.0f), 126.0f);
    return __fdividef(1.0f, 1.0f + fexp2(y));
}

// ---------------- init ---------------------------------------------------
__global__ void k_init(const float* __restrict__ dec, const float* __restrict__ h0,
                       const float* __restrict__ c0) {
    int i = blockIdx.x * blockDim.x + threadIdx.x;
    if (i < BB * KK2) {
        int b = i >> 9, k = i & 511;
        g_xh0[i] = (k < EE) ? dec[b * EE + k] : h0[b * HH + (k - EE)];
    }
    if (i < BB * HH)  g_c[i] = c0[i];
    if (i < BB * LLN) g_mask[i] = 0;
}

// ---------------- weight prep (one-time) ----------------------------------
// Wc row (4j+g) <- [Wih | Whh] row (g*256+j); bc = bih+bhh (same perm)
__global__ void k_prep_lstm(const float* __restrict__ Wih, const float* __restrict__ Whh,
                            const float* __restrict__ bih, const float* __restrict__ bhh) {
    int r = blockIdx.x;
    int j = r >> 2, g = r & 3;
    int src = g * HH + j;
    for (int k = threadIdx.x; k < EE; k += blockDim.x)
        g_Wc[(size_t)r * KK2 + k] = Wih[(size_t)src * EE + k];
    for (int k = threadIdx.x; k < HH; k += blockDim.x)
        g_Wc[(size_t)r * KK2 + EE + k] = Whh[(size_t)src * HH + k];
    if (threadIdx.x == 0) g_bc[r] = bih[src] + bhh[src];
}

// ---------------- generic NT GEMM with G->reg prefetch --------------------
struct GA { const float* A; int lda; const float* W; int wlda;
            const float* bias; float* C; };

template <int BM, int BN, int BK, int TM, int TN>
__global__ void gemm_multi(GA a0, GA a1, int N, int K) {
    constexpr int THREADS = (BM / TM) * (BN / TN);
    constexpr int A_LDS = BM * BK / THREADS / 4;
    constexpr int W_LDS = BN * BK / THREADS / 4;

    GA g = (blockIdx.z == 0) ? a0 : a1;

    __shared__ __align__(16) float As[BK][BM];
    __shared__ __align__(16) float Ws[BK][BN];

    const int tid = threadIdx.x;
    const int tx  = tid % (BN / TN);
    const int ty  = tid / (BN / TN);
    const int m0  = blockIdx.y * BM;
    const int n0  = blockIdx.x * BN;

    u64 acc[TM][TN / 2];
#pragma unroll
    for (int i = 0; i < TM; i++)
#pragma unroll
        for (int j = 0; j < TN / 2; j++) acc[i][j] = pk2(0.f, 0.f);

    float4 pa[A_LDS], pw[W_LDS];
#pragma unroll
    for (int i = 0; i < A_LDS; i++) {
        int li = tid + i * THREADS;
        pa[i] = *(const float4*)(g.A + (size_t)(m0 + li / (BK / 4)) * g.lda + (li % (BK / 4)) * 4);
    }
#pragma unroll
    for (int i = 0; i < W_LDS; i++) {
        int li = tid + i * THREADS;
        pw[i] = *(const float4*)(g.W + (size_t)(n0 + li / (BK / 4)) * g.wlda + (li % (BK / 4)) * 4);
    }

    for (int k0 = 0; k0 < K; k0 += BK) {
#pragma unroll
        for (int i = 0; i < A_LDS; i++) {
            int li = tid + i * THREADS;
            int r = li / (BK / 4), c4 = li % (BK / 4);
            As[c4 * 4 + 0][r] = pa[i].x; As[c4 * 4 + 1][r] = pa[i].y;
            As[c4 * 4 + 2][r] = pa[i].z; As[c4 * 4 + 3][r] = pa[i].w;
        }
#pragma unroll
        for (int i = 0; i < W_LDS; i++) {
            int li = tid + i * THREADS;
            int r = li / (BK / 4), c4 = li % (BK / 4);
            Ws[c4 * 4 + 0][r] = pw[i].x; Ws[c4 * 4 + 1][r] = pw[i].y;
            Ws[c4 * 4 + 2][r] = pw[i].z; Ws[c4 * 4 + 3][r] = pw[i].w;
        }
        __syncthreads();

        if (k0 + BK < K) {
#pragma unroll
            for (int i = 0; i < A_LDS; i++) {
                int li = tid + i * THREADS;
                pa[i] = *(const float4*)(g.A + (size_t)(m0 + li / (BK / 4)) * g.lda
                                         + k0 + BK + (li % (BK / 4)) * 4);
            }
#pragma unroll
            for (int i = 0; i < W_LDS; i++) {
                int li = tid + i * THREADS;
                pw[i] = *(const float4*)(g.W + (size_t)(n0 + li / (BK / 4)) * g.wlda
                                         + k0 + BK + (li % (BK / 4)) * 4);
            }
        }

#pragma unroll
        for (int kk = 0; kk < BK; kk++) {
            u64 bp[TN / 2];
#pragma unroll
            for (int j = 0; j < TN / 4; j++) {
                float4 wv = *(const float4*)&Ws[kk][tx * TN + j * 4];
                bp[2 * j]     = pk2(wv.x, wv.y);
                bp[2 * j + 1] = pk2(wv.z, wv.w);
            }
#pragma unroll
            for (int i = 0; i < TM; i += 4) {
                float4 av = *(const float4*)&As[kk][ty * TM + i];
                u64 q0 = pkdup(av.x), q1 = pkdup(av.y), q2 = pkdup(av.z), q3 = pkdup(av.w);
#pragma unroll
                for (int j = 0; j < TN / 2; j++) {
                    acc[i + 0][j] = ffma2(q0, bp[j], acc[i + 0][j]);
                    acc[i + 1][j] = ffma2(q1, bp[j], acc[i + 1][j]);
                    acc[i + 2][j] = ffma2(q2, bp[j], acc[i + 2][j]);
                    acc[i + 3][j] = ffma2(q3, bp[j], acc[i + 3][j]);
                }
            }
        }
        __syncthreads();
    }

    const int n = n0 + tx * TN;
    float bb[TN];
#pragma unroll
    for (int j = 0; j < TN; j++) bb[j] = g.bias[n + j];
#pragma unroll
    for (int i = 0; i < TM; i++) {
        int m = m0 + ty * TM + i;
#pragma unroll
        for (int j = 0; j < TN / 4; j++) {
            float2 u0 = upk(acc[i][2 * j]);
            float2 u1 = upk(acc[i][2 * j + 1]);
            float4 r;
            r.x = u0.x + bb[4 * j];     r.y = u0.y + bb[4 * j + 1];
            r.z = u1.x + bb[4 * j + 2]; r.w = u1.y + bb[4 * j + 3];
            *(float4*)(g.C + (size_t)m * N + n + 4 * j) = r;
        }
    }
}

// ---------------- LSTM cell: combine split-K partials + nonlinearity -------
// Gate-interleaved layout: G[b, 4j+{0,1,2,3}] = (i,f,g,o) of unit j -> float4.
__global__ void k_cell(float* __restrict__ xh_next) {
    int b = blockIdx.x, j = threadIdx.x;          // 1024 x 256
    const float4 a  = *(const float4*)(g_G1 + (size_t)b * H4 + 4 * j);
    const float4 d  = *(const float4*)(g_G2 + (size_t)b * H4 + 4 * j);
    const float4 bc = *(const float4*)(g_bc + 4 * j);
    float gi = a.x + d.x + bc.x;
    float gf = a.y + d.y + bc.y;
    float gg = a.z + d.z + bc.z;
    float go = a.w + d.w + bc.w;
    float c  = g_c[(size_t)b * HH + j];
    float c2 = sigm(gf) * c + sigm(gi) * fast_tanh(gg);
    g_c[(size_t)b * HH + j] = c2;
    xh_next[(size_t)b * KK2 + EE + j] = sigm(go) * fast_tanh(c2);
}

// ------ glimpse attention: u, masked softmax, combine IN e-SPACE -> g ------
__global__ void k_attn_gl(const float* __restrict__ v) {
    int b = blockIdx.x, tid = threadIdx.x, lane = tid & 31, w = tid >> 5;
    __shared__ __align__(16) float qs[HH], vs[HH];
    __shared__ float sp[LLN];
    __shared__ float s_inv;
    qs[tid] = g_qgl[(size_t)b * HH + tid];
    vs[tid] = v[tid];
    __syncthreads();

    const float* eb = g_e_gl + (size_t)b * HH;
    const float4* q4 = (const float4*)qs;
    const float4* v4 = (const float4*)vs;
    for (int l = w; l < LLN; l += 8) {
        const float4* er = (const float4*)(eb + (size_t)l * BB * HH);
        float4 e0 = er[lane * 2], e1 = er[lane * 2 + 1];
        float4 q0 = q4[lane * 2], q1 = q4[lane * 2 + 1];
        float4 vv0 = v4[lane * 2], vv1 = v4[lane * 2 + 1];
        float s = fast_tanh(q0.x + e0.x) * vv0.x + fast_tanh(q0.y + e0.y) * vv0.y
                + fast_tanh(q0.z + e0.z) * vv0.z + fast_tanh(q0.w + e0.w) * vv0.w
                + fast_tanh(q1.x + e1.x) * vv1.x + fast_tanh(q1.y + e1.y) * vv1.y
                + fast_tanh(q1.z + e1.z) * vv1.z + fast_tanh(q1.w + e1.w) * vv1.w;
#pragma unroll
        for (int o = 16; o; o >>= 1) s += __shfl_xor_sync(0xffffffffu, s, o);
        if (lane == 0) sp[l] = g_mask[b * LLN + l] ? NEGV : s;
    }
    __syncthreads();
    if (w == 0) {
        float a  = (lane < LLN) ? sp[lane] : -FLT_MAX;
        float bb = (lane + 32 < LLN) ? sp[lane + 32] : -FLT_MAX;
        float m = fmaxf(a, bb);
#pragma unroll
        for (int o = 16; o; o >>= 1) m = fmaxf(m, __shfl_xor_sync(0xffffffffu, m, o));
        float ea  = (lane < LLN) ? __expf(a - m) : 0.f;
        float eb2 = (lane + 32 < LLN) ? __expf(bb - m) : 0.f;
        if (lane < LLN) sp[lane] = ea;
        if (lane + 32 < LLN) sp[lane + 32] = eb2;
        float s = ea + eb2;
#pragma unroll
        for (int o = 16; o; o >>= 1) s += __shfl_xor_sync(0xffffffffu, s, o);
        if (lane == 0) s_inv = __fdividef(1.f, s);
    }
    __syncthreads();
    float inv = s_inv;
    const float* ec = eb + tid;
    float a0 = 0.f, a1 = 0.f;
#pragma unroll
    for (int l = 0; l < LLN; l += 2) {
        a0 = fmaf(sp[l],     ec[(size_t) l      * BB * HH], a0);
        a1 = fmaf(sp[l + 1], ec[(size_t)(l + 1) * BB * HH], a1);
    }
    g_g[(size_t)b * HH + tid] = (a0 + a1) * inv;
}

// ---- pointer attention: log_softmax (-> out), argmax, gather, mask --------
__global__ void k_attn_pt(const float* __restrict__ v, const float* __restrict__ emb,
                          float* __restrict__ out, float* __restrict__ sel_out,
                          int t, int wsel, float* __restrict__ xh_next) {
    int b = blockIdx.x, tid = threadIdx.x, lane = tid & 31, w = tid >> 5;
    __shared__ __align__(16) float qs[HH], vs[HH];
    __shared__ float sp[LLN];
    __shared__ float s_lse;
    __shared__ int s_idx;
    qs[tid] = g_qpt[(size_t)b * HH + tid];
    vs[tid] = v[tid];
    __syncthreads();

    const float* eb = g_e_pt + (size_t)b * HH;
    const float4* q4 = (const float4*)qs;
    const float4* v4 = (const float4*)vs;
    for (int l = w; l < LLN; l += 8) {
        const float4* er = (const float4*)(eb + (size_t)l * BB * HH);
        float4 e0 = er[lane * 2], e1 = er[lane * 2 + 1];
        float4 q0 = q4[lane * 2], q1 = q4[lane * 2 + 1];
        float4 vv0 = v4[lane * 2], vv1 = v4[lane * 2 + 1];
        float s = fast_tanh(q0.x + e0.x) * vv0.x + fast_tanh(q0.y + e0.y) * vv0.y
                + fast_tanh(q0.z + e0.z) * vv0.z + fast_tanh(q0.w + e0.w) * vv0.w
                + fast_tanh(q1.x + e1.x) * vv1.x + fast_tanh(q1.y + e1.y) * vv1.y
                + fast_tanh(q1.z + e1.z) * vv1.z + fast_tanh(q1.w + e1.w) * vv1.w;
#pragma unroll
        for (int o = 16; o; o >>= 1) s += __shfl_xor_sync(0xffffffffu, s, o);
        if (lane == 0) sp[l] = g_mask[b * LLN + l] ? NEGV : (CEXPL * fast_tanh(s));
    }
    __syncthreads();
    if (w == 0) {
        float a  = (lane < LLN) ? sp[lane] : -FLT_MAX;           int ia = lane;
        float bb = (lane + 32 < LLN) ? sp[lane + 32] : -FLT_MAX; int ib = lane + 32;
        float m; int mi;
        if (bb > a) { m = bb; mi = ib; } else { m = a; mi = ia; }
#pragma unroll
        for (int o = 16; o; o >>= 1) {
            float om = __shfl_xor_sync(0xffffffffu, m, o);
            int   oi = __shfl_xor_sync(0xffffffffu, mi, o);
            if (om > m || (om == m && oi < mi)) { m = om; mi = oi; }
        }
        float s = ((lane < LLN) ? __expf(a - m) : 0.f)
                + ((lane + 32 < LLN) ? __expf(bb - m) : 0.f);
#pragma unroll
        for (int o = 16; o; o >>= 1) s += __shfl_xor_sync(0xffffffffu, s, o);
        if (lane == 0) { s_lse = m + __logf(s); s_idx = mi; }
    }
    __syncthreads();
    int idx = s_idx; float lse = s_lse;
    if (tid < LLN)
        out[((size_t)b * LLN + t) * LLN + tid] = sp[tid] - lse;
    xh_next[(size_t)b * KK2 + tid] = emb[((size_t)idx * BB + b) * EE + tid];
    if (tid == 0) {
        g_mask[b * LLN + idx] = 1;       // mask for NEXT step
        int cnt = 0;
#pragma unroll
        for (int l = 0; l < LLN; l++) cnt += g_mask[b * LLN + l];
        if (cnt == LLN) g_mask[b * LLN + LLN - 1] = 0;   // ref's all-true reset
        if (wsel) sel_out[b * LLN + t] = (float)idx;
    }
}

// -------------------------------- launch ----------------------------------
extern "C" void kernel_launch(void* const* d_in, const int* in_sizes, int n_in,
                              void* d_out, int out_size) {
    (void)in_sizes; (void)n_in;
    const float* dec  = (const float*)d_in[0];
    const float* emb  = (const float*)d_in[1];
    const float* h0   = (const float*)d_in[2];
    const float* c0   = (const float*)d_in[3];
    const float* ctx  = (const float*)d_in[4];
    const float* Wih  = (const float*)d_in[6];
    const float* Whh  = (const float*)d_in[7];
    const float* bih  = (const float*)d_in[8];
    const float* bhh  = (const float*)d_in[9];
    const float* glWq = (const float*)d_in[10];
    const float* glbq = (const float*)d_in[11];
    const float* glWr = (const float*)d_in[12];
    const float* glbr = (const float*)d_in[13];
    const float* glv  = (const float*)d_in[14];
    const float* ptWq = (const float*)d_in[15];
    const float* ptbq = (const float*)d_in[16];
    const float* ptWr = (const float*)d_in[17];
    const float* ptbr = (const float*)d_in[18];
    const float* ptv  = (const float*)d_in[19];
    float* out = (float*)d_out;

    float *pe_gl, *pe_pt, *pxh0, *pxh1, *pqgl, *pqpt, *pg, *pG1, *pG2, *pWc, *pzero;
    cudaGetSymbolAddress((void**)&pe_gl, g_e_gl);
    cudaGetSymbolAddress((void**)&pe_pt, g_e_pt);
    cudaGetSymbolAddress((void**)&pxh0,  g_xh0);
    cudaGetSymbolAddress((void**)&pxh1,  g_xh1);
    cudaGetSymbolAddress((void**)&pqgl,  g_qgl);
    cudaGetSymbolAddress((void**)&pqpt,  g_qpt);
    cudaGetSymbolAddress((void**)&pg,    g_g);
    cudaGetSymbolAddress((void**)&pG1,   g_G1);
    cudaGetSymbolAddress((void**)&pG2,   g_G2);
    cudaGetSymbolAddress((void**)&pWc,   g_Wc);
    cudaGetSymbolAddress((void**)&pzero, g_zero);

    k_init<<<2048, 256>>>(dec, h0, c0);
    k_prep_lstm<<<H4, 256>>>(Wih, Whh, bih, bhh);

    // Time-invariant projections (z=2): e_gl = ctx@glWr^T+glbr ; e_pt = ctx@ptWr^T+ptbr
    {
        GA a0{ctx, HH, glWr, HH, glbr, pe_gl};
        GA a1{ctx, HH, ptWr, HH, ptbr, pe_pt};
        dim3 g(HH / 128, (LLN * BB) / 128, 2);
        gemm_multi<128, 128, 16, 8, 8><<<g, 256>>>(a0, a1, HH, HH);
    }

    const size_t BLLL = (size_t)BB * LLN * LLN;
    const int wsel = (out_size >= (int)(BLLL + (size_t)BB * LLN)) ? 1 : 0;

    float* xh[2] = {pxh0, pxh1};
    for (int t = 0; t < LLN; t++) {
        float* cur = xh[t & 1];
        float* nxt = xh[(t + 1) & 1];
        // LSTM gates, split-K in one launch (z=0: x-part, z=1: h-part) -> G1, G2
        {
            GA ax{cur,      KK2, pWc,      KK2, pzero, pG1};
            GA ah{cur + EE, KK2, pWc + EE, KK2, pzero, pG2};
            dim3 g(H4 / 64, BB / 64, 2);   // 512 CTAs, 2048 warps
            gemm_multi<64, 64, 16, 8, 4><<<g, 128>>>(ax, ah, H4, EE);
        }
        // cell nonlinearity: h_t -> nxt[:,256:512], c update
        k_cell<<<BB, HH>>>(nxt);
        // q_gl = h_t @ glWq^T + glbq
        {
            GA a{nxt + EE, KK2, glWq, HH, glbq, pqgl};
            gemm_multi<32, 64, 16, 4, 4><<<dim3(HH / 64, BB / 32, 1), 128>>>(a, a, HH, HH);
        }
        // glimpse attention -> g
        k_attn_gl<<<BB, HH>>>(glv);
        // q_pt = g @ ptWq^T + ptbq
        {
            GA a{pg, HH, ptWq, HH, ptbq, pqpt};
            gemm_multi<32, 64, 16, 4, 4><<<dim3(HH / 64, BB / 32, 1), 128>>>(a, a, HH, HH);
        }
        // pointer attention: log_p -> out, argmax, gather x_{t+1}, mask update
        k_attn_pt<<<BB, HH>>>(ptv, emb, out, out + BLLL, t, wsel, nxt);
    }
}

// round 7
// speedup vs baseline: 1.7388x; 1.1460x over previous
#include <cuda_runtime.h>
#include <math.h>
#include <float.h>

#define BB 1024
#define LLN 50
#define EE 256
#define HH 256
#define KK2 512          // E + H
#define H4 1024
#define NEGV (-1e9f)
#define CEXPL 10.0f

typedef unsigned long long u64;

// ---------------- device scratch (no allocations allowed) ----------------
__device__ __align__(16) float g_e_gl[(size_t)LLN * BB * HH];  // 52.4 MB
__device__ __align__(16) float g_e_pt[(size_t)LLN * BB * HH];  // 52.4 MB
__device__ __align__(16) float g_xh0[BB * KK2];                // [x | h] ping
__device__ __align__(16) float g_xh1[BB * KK2];                // [x | h] pong
__device__ __align__(16) float g_c  [BB * HH];
__device__ __align__(16) float g_qgl0[BB * HH];
__device__ __align__(16) float g_qgl1[BB * HH];
__device__ __align__(16) float g_g   [BB * HH];
__device__ __align__(16) float g_qpt0[BB * HH];
__device__ __align__(16) float g_qpt1[BB * HH];
__device__ __align__(16) float g_G  [(size_t)4 * BB * H4];     // split-K x4 partials, 16MB
__device__ __align__(16) float g_Wc [H4 * KK2];                // gate-interleaved [Wih|Whh]
__device__ __align__(16) float g_bc [H4];
__device__ __align__(16) float g_zero[H4];                     // static zero bias
__device__ unsigned char g_mask[BB * LLN];

// ---------------- packed fp32x2 FMA helpers (IEEE-exact) ------------------
__device__ __forceinline__ u64 pk2(float x, float y) {
    u64 r; asm("mov.b64 %0,{%1,%2};" : "=l"(r) : "f"(x), "f"(y)); return r;
}
__device__ __forceinline__ u64 pkdup(float x) {
    u64 r; asm("mov.b64 %0,{%1,%1};" : "=l"(r) : "f"(x)); return r;
}
__device__ __forceinline__ u64 ffma2(u64 a, u64 b, u64 c) {
    u64 d; asm("fma.rn.f32x2 %0,%1,%2,%3;" : "=l"(d) : "l"(a), "l"(b), "l"(c)); return d;
}
__device__ __forceinline__ float2 upk(u64 a) {
    float2 f; asm("mov.b64 {%0,%1},%2;" : "=f"(f.x), "=f"(f.y) : "l"(a)); return f;
}

// ---------------- FMA-pipe exp2 (deg-7 Horner, rel err ~1e-8) -------------
__device__ __forceinline__ float fexp2(float y) {
    float k = y + 12582912.0f;              // RN round-to-int via magic
    float f = y - (k - 12582912.0f);        // f in [-0.5, 0.5], exact
    float p =            1.5252734e-5f;
    p = fmaf(p, f, 1.5403530e-4f);
    p = fmaf(p, f, 1.3333558e-3f);
    p = fmaf(p, f, 9.6181291e-3f);
    p = fmaf(p, f, 5.5504109e-2f);
    p = fmaf(p, f, 2.4022651e-1f);
    p = fmaf(p, f, 6.9314718e-1f);
    p = fmaf(p, f, 1.0f);
    float sc = __int_as_float((__float_as_int(k) - 1262485377) << 23);
    return p * sc;
}

// tanh with 1 MUFU (rcp) ; rel err ~1e-7
__device__ __forceinline__ float fast_tanh(float x) {
    float ax = fabsf(x);
    float y  = fminf(ax * 2.8853901f, 126.0f);   // 2*log2(e)*ax
    float e2 = fexp2(y);
    float r  = 1.0f - __fdividef(2.0f, e2 + 1.0f);
    return copysignf(r, x);
}
__device__ __forceinline__ float sigm(float x) {
    float y = fminf(fmaxf(-x * 1.4426950f, -126.0f), 126.0f);
    return __fdividef(1.0f, 1.0f + fexp2(y));
}

// ---------------- init ---------------------------------------------------
__global__ void k_init(const float* __restrict__ dec, const float* __restrict__ h0,
                       const float* __restrict__ c0) {
    int i = blockIdx.x * blockDim.x + threadIdx.x;
    if (i < BB * KK2) {
        int b = i >> 9, k = i & 511;
        g_xh0[i] = (k < EE) ? dec[b * EE + k] : h0[b * HH + (k - EE)];
    }
    if (i < BB * HH)  g_c[i] = c0[i];
    if (i < BB * LLN) g_mask[i] = 0;
}

// ---------------- weight prep (one-time) ----------------------------------
// Wc row (4j+g) <- [Wih | Whh] row (g*256+j); bc = bih+bhh (same perm)
__global__ void k_prep_lstm(const float* __restrict__ Wih, const float* __restrict__ Whh,
                            const float* __restrict__ bih, const float* __restrict__ bhh) {
    int r = blockIdx.x;
    int j = r >> 2, g = r & 3;
    int src = g * HH + j;
    for (int k = threadIdx.x; k < EE; k += blockDim.x)
        g_Wc[(size_t)r * KK2 + k] = Wih[(size_t)src * EE + k];
    for (int k = threadIdx.x; k < HH; k += blockDim.x)
        g_Wc[(size_t)r * KK2 + EE + k] = Whh[(size_t)src * HH + k];
    if (threadIdx.x == 0) g_bc[r] = bih[src] + bhh[src];
}

// ---------------- generic NT GEMM with G->reg prefetch --------------------
struct GA { const float* A; int lda; const float* W; int wlda;
            const float* bias; float* C; };

template <int BM, int BN, int BK, int TM, int TN>
__global__ void gemm_multi(GA a0, GA a1, int N, int K) {
    constexpr int THREADS = (BM / TM) * (BN / TN);
    constexpr int A_LDS = BM * BK / THREADS / 4;
    constexpr int W_LDS = BN * BK / THREADS / 4;

    GA g = (blockIdx.z == 0) ? a0 : a1;

    __shared__ __align__(16) float As[BK][BM];
    __shared__ __align__(16) float Ws[BK][BN];

    const int tid = threadIdx.x;
    const int tx  = tid % (BN / TN);
    const int ty  = tid / (BN / TN);
    const int m0  = blockIdx.y * BM;
    const int n0  = blockIdx.x * BN;

    u64 acc[TM][TN / 2];
#pragma unroll
    for (int i = 0; i < TM; i++)
#pragma unroll
        for (int j = 0; j < TN / 2; j++) acc[i][j] = pk2(0.f, 0.f);

    float4 pa[A_LDS], pw[W_LDS];
#pragma unroll
    for (int i = 0; i < A_LDS; i++) {
        int li = tid + i * THREADS;
        pa[i] = *(const float4*)(g.A + (size_t)(m0 + li / (BK / 4)) * g.lda + (li % (BK / 4)) * 4);
    }
#pragma unroll
    for (int i = 0; i < W_LDS; i++) {
        int li = tid + i * THREADS;
        pw[i] = *(const float4*)(g.W + (size_t)(n0 + li / (BK / 4)) * g.wlda + (li % (BK / 4)) * 4);
    }

    for (int k0 = 0; k0 < K; k0 += BK) {
#pragma unroll
        for (int i = 0; i < A_LDS; i++) {
            int li = tid + i * THREADS;
            int r = li / (BK / 4), c4 = li % (BK / 4);
            As[c4 * 4 + 0][r] = pa[i].x; As[c4 * 4 + 1][r] = pa[i].y;
            As[c4 * 4 + 2][r] = pa[i].z; As[c4 * 4 + 3][r] = pa[i].w;
        }
#pragma unroll
        for (int i = 0; i < W_LDS; i++) {
            int li = tid + i * THREADS;
            int r = li / (BK / 4), c4 = li % (BK / 4);
            Ws[c4 * 4 + 0][r] = pw[i].x; Ws[c4 * 4 + 1][r] = pw[i].y;
            Ws[c4 * 4 + 2][r] = pw[i].z; Ws[c4 * 4 + 3][r] = pw[i].w;
        }
        __syncthreads();

        if (k0 + BK < K) {
#pragma unroll
            for (int i = 0; i < A_LDS; i++) {
                int li = tid + i * THREADS;
                pa[i] = *(const float4*)(g.A + (size_t)(m0 + li / (BK / 4)) * g.lda
                                         + k0 + BK + (li % (BK / 4)) * 4);
            }
#pragma unroll
            for (int i = 0; i < W_LDS; i++) {
                int li = tid + i * THREADS;
                pw[i] = *(const float4*)(g.W + (size_t)(n0 + li / (BK / 4)) * g.wlda
                                         + k0 + BK + (li % (BK / 4)) * 4);
            }
        }

#pragma unroll
        for (int kk = 0; kk < BK; kk++) {
            u64 bp[TN / 2];
#pragma unroll
            for (int j = 0; j < TN / 4; j++) {
                float4 wv = *(const float4*)&Ws[kk][tx * TN + j * 4];
                bp[2 * j]     = pk2(wv.x, wv.y);
                bp[2 * j + 1] = pk2(wv.z, wv.w);
            }
#pragma unroll
            for (int i = 0; i < TM; i += 4) {
                float4 av = *(const float4*)&As[kk][ty * TM + i];
                u64 q0 = pkdup(av.x), q1 = pkdup(av.y), q2 = pkdup(av.z), q3 = pkdup(av.w);
#pragma unroll
                for (int j = 0; j < TN / 2; j++) {
                    acc[i + 0][j] = ffma2(q0, bp[j], acc[i + 0][j]);
                    acc[i + 1][j] = ffma2(q1, bp[j], acc[i + 1][j]);
                    acc[i + 2][j] = ffma2(q2, bp[j], acc[i + 2][j]);
                    acc[i + 3][j] = ffma2(q3, bp[j], acc[i + 3][j]);
                }
            }
        }
        __syncthreads();
    }

    const int n = n0 + tx * TN;
    float bb[TN];
#pragma unroll
    for (int j = 0; j < TN; j++) bb[j] = g.bias[n + j];
#pragma unroll
    for (int i = 0; i < TM; i++) {
        int m = m0 + ty * TM + i;
#pragma unroll
        for (int j = 0; j < TN / 4; j++) {
            float2 u0 = upk(acc[i][2 * j]);
            float2 u1 = upk(acc[i][2 * j + 1]);
            float4 r;
            r.x = u0.x + bb[4 * j];     r.y = u0.y + bb[4 * j + 1];
            r.z = u1.x + bb[4 * j + 2]; r.w = u1.y + bb[4 * j + 3];
            *(float4*)(g.C + (size_t)m * N + n + 4 * j) = r;
        }
    }
}

// ---------------- LSTM gates, split-K x4 -----------------------------------
// z = blockIdx.z selects K-window [z*128, (z+1)*128); writes g_G[z].
// BM=64, BN=64, BK=16, TM=8, TN=4, 128 thr -> grid (16,16,4) = 1024 CTAs.
__global__ void k_lstm4(const float* __restrict__ A0) {
    constexpr int BM = 64, BN = 64, BK = 16, TM = 8, KS = 128;
    constexpr int THREADS = 128;

    __shared__ __align__(16) float As[BK][BM];
    __shared__ __align__(16) float Ws[BK][BN];

    const int tid = threadIdx.x;
    const int tx  = tid % 16;           // BN/TN
    const int ty  = tid / 16;
    const int m0  = blockIdx.y * BM;
    const int n0  = blockIdx.x * BN;
    const int z   = blockIdx.z;

    const float* A = A0 + z * KS;            // row stride KK2
    const float* W = g_Wc + z * KS;          // row stride KK2
    float* C = g_G + (size_t)z * BB * H4;

    u64 acc[TM][2];
#pragma unroll
    for (int i = 0; i < TM; i++) { acc[i][0] = pk2(0.f, 0.f); acc[i][1] = pk2(0.f, 0.f); }

    float4 pa[2], pw[2];                 // A_LDS = W_LDS = 64*16/128/4 = 2
#pragma unroll
    for (int i = 0; i < 2; i++) {
        int li = tid + i * THREADS;
        pa[i] = *(const float4*)(A + (size_t)(m0 + li / 4) * KK2 + (li % 4) * 4);
        pw[i] = *(const float4*)(W + (size_t)(n0 + li / 4) * KK2 + (li % 4) * 4);
    }

    for (int k0 = 0; k0 < KS; k0 += BK) {
#pragma unroll
        for (int i = 0; i < 2; i++) {
            int li = tid + i * THREADS;
            int r = li / 4, c4 = li % 4;
            As[c4 * 4 + 0][r] = pa[i].x; As[c4 * 4 + 1][r] = pa[i].y;
            As[c4 * 4 + 2][r] = pa[i].z; As[c4 * 4 + 3][r] = pa[i].w;
            Ws[c4 * 4 + 0][r] = pw[i].x; Ws[c4 * 4 + 1][r] = pw[i].y;
            Ws[c4 * 4 + 2][r] = pw[i].z; Ws[c4 * 4 + 3][r] = pw[i].w;
        }
        __syncthreads();

        if (k0 + BK < KS) {
#pragma unroll
            for (int i = 0; i < 2; i++) {
                int li = tid + i * THREADS;
                pa[i] = *(const float4*)(A + (size_t)(m0 + li / 4) * KK2
                                         + k0 + BK + (li % 4) * 4);
                pw[i] = *(const float4*)(W + (size_t)(n0 + li / 4) * KK2
                                         + k0 + BK + (li % 4) * 4);
            }
        }

#pragma unroll
        for (int kk = 0; kk < BK; kk++) {
            float4 bv = *(const float4*)&Ws[kk][tx * 4];
            u64 bp0 = pk2(bv.x, bv.y);
            u64 bp1 = pk2(bv.z, bv.w);
#pragma unroll
            for (int i = 0; i < TM; i += 4) {
                float4 av = *(const float4*)&As[kk][ty * TM + i];
                u64 q0 = pkdup(av.x), q1 = pkdup(av.y), q2 = pkdup(av.z), q3 = pkdup(av.w);
                acc[i + 0][0] = ffma2(q0, bp0, acc[i + 0][0]);
                acc[i + 0][1] = ffma2(q0, bp1, acc[i + 0][1]);
                acc[i + 1][0] = ffma2(q1, bp0, acc[i + 1][0]);
                acc[i + 1][1] = ffma2(q1, bp1, acc[i + 1][1]);
                acc[i + 2][0] = ffma2(q2, bp0, acc[i + 2][0]);
                acc[i + 2][1] = ffma2(q2, bp1, acc[i + 2][1]);
                acc[i + 3][0] = ffma2(q3, bp0, acc[i + 3][0]);
                acc[i + 3][1] = ffma2(q3, bp1, acc[i + 3][1]);
            }
        }
        __syncthreads();
    }

    const int n = n0 + tx * 4;
#pragma unroll
    for (int i = 0; i < TM; i++) {
        int m = m0 + ty * TM + i;
        float2 u0 = upk(acc[i][0]);
        float2 u1 = upk(acc[i][1]);
        float4 r; r.x = u0.x; r.y = u0.y; r.z = u1.x; r.w = u1.y;
        *(float4*)(C + (size_t)m * H4 + n) = r;
    }
}

// ---------------- LSTM cell: sum 4 split-K partials + nonlinearity ---------
__global__ void k_cell(float* __restrict__ xh_next) {
    int b = blockIdx.x, j = threadIdx.x;          // 1024 x 256
    size_t off = (size_t)b * H4 + 4 * j;
    const float4 p0 = *(const float4*)(g_G + off);
    const float4 p1 = *(const float4*)(g_G + (size_t)1 * BB * H4 + off);
    const float4 p2 = *(const float4*)(g_G + (size_t)2 * BB * H4 + off);
    const float4 p3 = *(const float4*)(g_G + (size_t)3 * BB * H4 + off);
    const float4 bc = *(const float4*)(g_bc + 4 * j);
    float gi = (p0.x + p1.x) + (p2.x + p3.x) + bc.x;
    float gf = (p0.y + p1.y) + (p2.y + p3.y) + bc.y;
    float gg = (p0.z + p1.z) + (p2.z + p3.z) + bc.z;
    float go = (p0.w + p1.w) + (p2.w + p3.w) + bc.w;
    float c  = g_c[(size_t)b * HH + j];
    float c2 = sigm(gf) * c + sigm(gi) * fast_tanh(gg);
    g_c[(size_t)b * HH + j] = c2;
    xh_next[(size_t)b * KK2 + EE + j] = sigm(go) * fast_tanh(c2);
}

// ------ glimpse attention: u, masked softmax, combine IN e-SPACE -> g ------
__global__ void k_attn_gl(const float* __restrict__ v) {
    int b = blockIdx.x, tid = threadIdx.x, lane = tid & 31, w = tid >> 5;
    __shared__ __align__(16) float qs[HH], vs[HH];
    __shared__ float sp[LLN];
    __shared__ float s_inv;
    qs[tid] = g_qgl0[(size_t)b * HH + tid] + g_qgl1[(size_t)b * HH + tid];
    vs[tid] = v[tid];
    __syncthreads();

    const float* eb = g_e_gl + (size_t)b * HH;
    const float4* q4 = (const float4*)qs;
    const float4* v4 = (const float4*)vs;
    for (int l = w; l < LLN; l += 8) {
        const float4* er = (const float4*)(eb + (size_t)l * BB * HH);
        float4 e0 = er[lane * 2], e1 = er[lane * 2 + 1];
        float4 q0 = q4[lane * 2], q1 = q4[lane * 2 + 1];
        float4 vv0 = v4[lane * 2], vv1 = v4[lane * 2 + 1];
        float s = fast_tanh(q0.x + e0.x) * vv0.x + fast_tanh(q0.y + e0.y) * vv0.y
                + fast_tanh(q0.z + e0.z) * vv0.z + fast_tanh(q0.w + e0.w) * vv0.w
                + fast_tanh(q1.x + e1.x) * vv1.x + fast_tanh(q1.y + e1.y) * vv1.y
                + fast_tanh(q1.z + e1.z) * vv1.z + fast_tanh(q1.w + e1.w) * vv1.w;
#pragma unroll
        for (int o = 16; o; o >>= 1) s += __shfl_xor_sync(0xffffffffu, s, o);
        if (lane == 0) sp[l] = g_mask[b * LLN + l] ? NEGV : s;
    }
    __syncthreads();
    if (w == 0) {
        float a  = (lane < LLN) ? sp[lane] : -FLT_MAX;
        float bb = (lane + 32 < LLN) ? sp[lane + 32] : -FLT_MAX;
        float m = fmaxf(a, bb);
#pragma unroll
        for (int o = 16; o; o >>= 1) m = fmaxf(m, __shfl_xor_sync(0xffffffffu, m, o));
        float ea  = (lane < LLN) ? __expf(a - m) : 0.f;
        float eb2 = (lane + 32 < LLN) ? __expf(bb - m) : 0.f;
        if (lane < LLN) sp[lane] = ea;
        if (lane + 32 < LLN) sp[lane + 32] = eb2;
        float s = ea + eb2;
#pragma unroll
        for (int o = 16; o; o >>= 1) s += __shfl_xor_sync(0xffffffffu, s, o);
        if (lane == 0) s_inv = __fdividef(1.f, s);
    }
    __syncthreads();
    float inv = s_inv;
    const float* ec = eb + tid;
    float a0 = 0.f, a1 = 0.f;
#pragma unroll
    for (int l = 0; l < LLN; l += 2) {
        a0 = fmaf(sp[l],     ec[(size_t) l      * BB * HH], a0);
        a1 = fmaf(sp[l + 1], ec[(size_t)(l + 1) * BB * HH], a1);
    }
    g_g[(size_t)b * HH + tid] = (a0 + a1) * inv;
}

// ---- pointer attention: log_softmax (-> out), argmax, gather, mask --------
__global__ void k_attn_pt(const float* __restrict__ v, const float* __restrict__ emb,
                          float* __restrict__ out, float* __restrict__ sel_out,
                          int t, int wsel, float* __restrict__ xh_next) {
    int b = blockIdx.x, tid = threadIdx.x, lane = tid & 31, w = tid >> 5;
    __shared__ __align__(16) float qs[HH], vs[HH];
    __shared__ float sp[LLN];
    __shared__ float s_lse;
    __shared__ int s_idx;
    qs[tid] = g_qpt0[(size_t)b * HH + tid] + g_qpt1[(size_t)b * HH + tid];
    vs[tid] = v[tid];
    __syncthreads();

    const float* eb = g_e_pt + (size_t)b * HH;
    const float4* q4 = (const float4*)qs;
    const float4* v4 = (const float4*)vs;
    for (int l = w; l < LLN; l += 8) {
        const float4* er = (const float4*)(eb + (size_t)l * BB * HH);
        float4 e0 = er[lane * 2], e1 = er[lane * 2 + 1];
        float4 q0 = q4[lane * 2], q1 = q4[lane * 2 + 1];
        float4 vv0 = v4[lane * 2], vv1 = v4[lane * 2 + 1];
        float s = fast_tanh(q0.x + e0.x) * vv0.x + fast_tanh(q0.y + e0.y) * vv0.y
                + fast_tanh(q0.z + e0.z) * vv0.z + fast_tanh(q0.w + e0.w) * vv0.w
                + fast_tanh(q1.x + e1.x) * vv1.x + fast_tanh(q1.y + e1.y) * vv1.y
                + fast_tanh(q1.z + e1.z) * vv1.z + fast_tanh(q1.w + e1.w) * vv1.w;
#pragma unroll
        for (int o = 16; o; o >>= 1) s += __shfl_xor_sync(0xffffffffu, s, o);
        if (lane == 0) sp[l] = g_mask[b * LLN + l] ? NEGV : (CEXPL * fast_tanh(s));
    }
    __syncthreads();
    if (w == 0) {
        float a  = (lane < LLN) ? sp[lane] : -FLT_MAX;           int ia = lane;
        float bb = (lane + 32 < LLN) ? sp[lane + 32] : -FLT_MAX; int ib = lane + 32;
        float m; int mi;
        if (bb > a) { m = bb; mi = ib; } else { m = a; mi = ia; }
#pragma unroll
        for (int o = 16; o; o >>= 1) {
            float om = __shfl_xor_sync(0xffffffffu, m, o);
            int   oi = __shfl_xor_sync(0xffffffffu, mi, o);
            if (om > m || (om == m && oi < mi)) { m = om; mi = oi; }
        }
        float s = ((lane < LLN) ? __expf(a - m) : 0.f)
                + ((lane + 32 < LLN) ? __expf(bb - m) : 0.f);
#pragma unroll
        for (int o = 16; o; o >>= 1) s += __shfl_xor_sync(0xffffffffu, s, o);
        if (lane == 0) { s_lse = m + __logf(s); s_idx = mi; }
    }
    __syncthreads();
    int idx = s_idx; float lse = s_lse;
    if (tid < LLN)
        out[((size_t)b * LLN + t) * LLN + tid] = sp[tid] - lse;
    xh_next[(size_t)b * KK2 + tid] = emb[((size_t)idx * BB + b) * EE + tid];
    if (tid == 0) {
        g_mask[b * LLN + idx] = 1;       // mask for NEXT step
        int cnt = 0;
#pragma unroll
        for (int l = 0; l < LLN; l++) cnt += g_mask[b * LLN + l];
        if (cnt == LLN) g_mask[b * LLN + LLN - 1] = 0;   // ref's all-true reset
        if (wsel) sel_out[b * LLN + t] = (float)idx;
    }
}

// -------------------------------- launch ----------------------------------
extern "C" void kernel_launch(void* const* d_in, const int* in_sizes, int n_in,
                              void* d_out, int out_size) {
    (void)in_sizes; (void)n_in;
    const float* dec  = (const float*)d_in[0];
    const float* emb  = (const float*)d_in[1];
    const float* h0   = (const float*)d_in[2];
    const float* c0   = (const float*)d_in[3];
    const float* ctx  = (const float*)d_in[4];
    const float* Wih  = (const float*)d_in[6];
    const float* Whh  = (const float*)d_in[7];
    const float* bih  = (const float*)d_in[8];
    const float* bhh  = (const float*)d_in[9];
    const float* glWq = (const float*)d_in[10];
    const float* glbq = (const float*)d_in[11];
    const float* glWr = (const float*)d_in[12];
    const float* glbr = (const float*)d_in[13];
    const float* glv  = (const float*)d_in[14];
    const float* ptWq = (const float*)d_in[15];
    const float* ptbq = (const float*)d_in[16];
    const float* ptWr = (const float*)d_in[17];
    const float* ptbr = (const float*)d_in[18];
    const float* ptv  = (const float*)d_in[19];
    float* out = (float*)d_out;

    float *pe_gl, *pe_pt, *pxh0, *pxh1, *pg, *pzero;
    float *pqgl0, *pqgl1, *pqpt0, *pqpt1;
    cudaGetSymbolAddress((void**)&pe_gl, g_e_gl);
    cudaGetSymbolAddress((void**)&pe_pt, g_e_pt);
    cudaGetSymbolAddress((void**)&pxh0,  g_xh0);
    cudaGetSymbolAddress((void**)&pxh1,  g_xh1);
    cudaGetSymbolAddress((void**)&pg,    g_g);
    cudaGetSymbolAddress((void**)&pzero, g_zero);
    cudaGetSymbolAddress((void**)&pqgl0, g_qgl0);
    cudaGetSymbolAddress((void**)&pqgl1, g_qgl1);
    cudaGetSymbolAddress((void**)&pqpt0, g_qpt0);
    cudaGetSymbolAddress((void**)&pqpt1, g_qpt1);

    k_init<<<2048, 256>>>(dec, h0, c0);
    k_prep_lstm<<<H4, 256>>>(Wih, Whh, bih, bhh);

    // Time-invariant projections (z=2): e_gl = ctx@glWr^T+glbr ; e_pt = ctx@ptWr^T+ptbr
    {
        GA a0{ctx, HH, glWr, HH, glbr, pe_gl};
        GA a1{ctx, HH, ptWr, HH, ptbr, pe_pt};
        dim3 g(HH / 128, (LLN * BB) / 128, 2);
        gemm_multi<128, 128, 16, 8, 8><<<g, 256>>>(a0, a1, HH, HH);
    }

    const size_t BLLL = (size_t)BB * LLN * LLN;
    const int wsel = (out_size >= (int)(BLLL + (size_t)BB * LLN)) ? 1 : 0;

    float* xh[2] = {pxh0, pxh1};
    for (int t = 0; t < LLN; t++) {
        float* cur = xh[t & 1];
        float* nxt = xh[(t + 1) & 1];
        // LSTM gates, split-K x4 -> g_G[0..3]; 1024 CTAs
        k_lstm4<<<dim3(H4 / 64, BB / 64, 4), 128>>>(cur);
        // cell: sum partials, nonlinearity, h_t -> nxt[:,256:512]
        k_cell<<<BB, HH>>>(nxt);
        // q_gl split-K x2 (bias in z=0; partials summed in k_attn_gl)
        {
            GA a0{nxt + EE,       KK2, glWq,       HH, glbq,  pqgl0};
            GA a1{nxt + EE + 128, KK2, glWq + 128, HH, pzero, pqgl1};
            gemm_multi<32, 64, 16, 4, 4><<<dim3(HH / 64, BB / 32, 2), 128>>>(a0, a1, HH, 128);
        }
        // glimpse attention -> g
        k_attn_gl<<<BB, HH>>>(glv);
        // q_pt split-K x2
        {
            GA a0{pg,       HH, ptWq,       HH, ptbq,  pqpt0};
            GA a1{pg + 128, HH, ptWq + 128, HH, pzero, pqpt1};
            gemm_multi<32, 64, 16, 4, 4><<<dim3(HH / 64, BB / 32, 2), 128>>>(a0, a1, HH, 128);
        }
        // pointer attention: log_p -> out, argmax, gather x_{t+1}, mask update
        k_attn_pt<<<BB, HH>>>(ptv, emb, out, out + BLLL, t, wsel, nxt);
    }
}